// round 9
// baseline (speedup 1.0000x reference)
#include <cuda_runtime.h>
#include <cuda_fp16.h>
#include <cstdint>
#include <math.h>

// Problem constants
#define BSZ   4
#define NLEN  4096
#define DIM_  1024
#define HEADS 16
#define HD    64
#define FEAT  256
#define ROWS  (BSZ * NLEN)   // 16384
#define GSPLIT 8

// ---------------- scratch (__device__ globals; no allocation allowed) ------
__device__ __align__(16) __half g_x16[(size_t)ROWS * DIM_];
__device__ __align__(16) __half g_q116[(size_t)ROWS * DIM_];
__device__ __align__(16) float g_k[(size_t)ROWS * DIM_];
__device__ __align__(16) float g_v[(size_t)ROWS * DIM_];
__device__ __align__(16) __half g_wt16[3][(size_t)DIM_ * DIM_];   // [Wq;Wk;Wv]^T fp16 (3072 x 1024)
__device__ __align__(16) __half g_w2t16[(size_t)BSZ * DIM_ * DIM_];
__device__ float g_Gpart[(size_t)GSPLIT * BSZ * HEADS * HD * HD];
__device__ float g_P[HD * HD];
__device__ float g_M[(size_t)BSZ * HEADS * HD * HD];

__device__ __forceinline__ float act_elu1(float x) {
    return x > 0.f ? x + 1.f : expf(x);
}

// ======================= PTX helpers (non-'a' ISA only) =====================
__device__ __forceinline__ uint32_t smem_u32(const void* p) {
    return (uint32_t)__cvta_generic_to_shared(p);
}

__device__ __forceinline__ void cp16(uint32_t smem, const void* g) {
    asm volatile("cp.async.cg.shared.global [%0], [%1], 16;\n" :: "r"(smem), "l"(g));
}
__device__ __forceinline__ void cp_commit() {
    asm volatile("cp.async.commit_group;\n" ::: "memory");
}
template <int N>
__device__ __forceinline__ void cp_wait() {
    asm volatile("cp.async.wait_group %0;\n" :: "n"(N) : "memory");
}

__device__ __forceinline__ void ldm_x4(uint32_t* r, uint32_t addr) {
    asm volatile("ldmatrix.sync.aligned.m8n8.x4.shared.b16 {%0,%1,%2,%3}, [%4];"
                 : "=r"(r[0]), "=r"(r[1]), "=r"(r[2]), "=r"(r[3]) : "r"(addr));
}

__device__ __forceinline__ void mma_fp16(float* c, const uint32_t* a, uint32_t b0, uint32_t b1) {
    asm volatile(
        "mma.sync.aligned.m16n8k16.row.col.f32.f16.f16.f32 "
        "{%0,%1,%2,%3}, {%4,%5,%6,%7}, {%8,%9}, {%0,%1,%2,%3};"
        : "+f"(c[0]), "+f"(c[1]), "+f"(c[2]), "+f"(c[3])
        : "r"(a[0]), "r"(a[1]), "r"(a[2]), "r"(a[3]), "r"(b0), "r"(b1));
}

__device__ __forceinline__ uint32_t hpack(float a, float b) {
    __half h0 = __float2half_rn(a), h1 = __float2half_rn(b);
    return (uint32_t)__half_as_ushort(h0) | ((uint32_t)__half_as_ushort(h1) << 16);
}

// ======================= conversion kernels ================================
__global__ __launch_bounds__(256) void conv_x_kernel(const float4* __restrict__ x,
                                                     uint2* __restrict__ xo, int n4)
{
    int i = blockIdx.x * 256 + threadIdx.x;
    if (i >= n4) return;
    float4 v = x[i];
    uint2 H;
    H.x = hpack(v.x, v.y);
    H.y = hpack(v.z, v.w);
    xo[i] = H;
}

// transpose + fp16: Wt[n,k] = W[k,n]; blockIdx.z selects Wq/Wk/Wv
__global__ __launch_bounds__(1024) void conv_w_kernel(const float* __restrict__ W0,
                                                      const float* __restrict__ W1,
                                                      const float* __restrict__ W2,
                                                      __half* __restrict__ Wt)
{
    __shared__ float t[32][33];
    const float* W = (blockIdx.z == 0) ? W0 : (blockIdx.z == 1) ? W1 : W2;
    int tx = threadIdx.x, ty = threadIdx.y;
    int k = blockIdx.y * 32 + ty, n = blockIdx.x * 32 + tx;
    t[ty][tx] = W[(long)k * DIM_ + n];
    __syncthreads();
    float v = t[tx][ty];
    long o = (long)blockIdx.z * DIM_ * DIM_
           + (long)(blockIdx.x * 32 + ty) * DIM_ + blockIdx.y * 32 + tx;
    Wt[o] = __float2half_rn(v);
}

// ======================= mma.sync fp16 GEMM =================================
// Block tile 256x128, BK=32, 8 warps (warp tile 64x64, 4x2), 4-stage cp.async.
// Stage = A(256x64B) + B(128x64B) with RSTRIDE pad = 30720 B; 4 stages = 120KB.
#define BK 32
#define RSTRIDE 80                       // 64B row + 16B pad (conflict-free ldmatrix)
#define BM 256
#define BN 128
#define SBOFF (BM * RSTRIDE)             // B region after A
#define STAGE_BYTES ((BM + BN) * RSTRIDE)   // 30720
#define NSTAGES 4
#define GEMM_SMEM (NSTAGES * STAGE_BYTES)

// FUSED==1: QKV — B is concatenated [Wq;Wk;Wv]^T (3072 x 1024); tile's N-range
//   selects output: q -> fp16 (+act), k -> fp32 (+act), v -> fp32.
// FUSED==0: final batched GEMM, fp32 out, no act; z = batch.
template <int FUSED>
__global__ __launch_bounds__(256, 1) void gemm_tc(
    const __half* __restrict__ Ax, const __half* __restrict__ Bx,
    const float* __restrict__ bias0, const float* __restrict__ bias1,
    const float* __restrict__ bias2,
    float* __restrict__ Cf_k, float* __restrict__ Cf_v,
    __half* __restrict__ Ch_q, float* __restrict__ Cf_out,
    int K, long sA, long sB, long sC)
{
    extern __shared__ char dynsmem[];
    const uint32_t sbase = smem_u32(dynsmem);

    const int tid = threadIdx.x;
    const int wid = tid >> 5, lane = tid & 31;
    const long z = blockIdx.z;
    if (!FUSED) { Ax += z * sA; Bx += z * sB; }

    const int tileM = blockIdx.y * BM;
    const int tileN = blockIdx.x * BN;
    const int wm = (wid >> 1) * 64;      // warp M offset in tile (4 groups)
    const int wn = (wid & 1) * 64;       // warp N offset in tile (2 groups)

    // output selection (uniform per CTA)
    int sel;                             // 0:q 1:k 2:v 3:final
    int coln_base;
    const float* bias;
    if (FUSED) {
        sel = tileN >> 10;
        coln_base = tileN & 1023;
        bias = (sel == 0) ? bias0 : (sel == 1) ? bias1 : bias2;
    } else {
        sel = 3;
        coln_base = tileN;
        bias = bias0;
    }

    const int NCH = K / BK;

    // ---- loader: 1536 x 16B granules per stage (A 1024 + B 512) ----
    auto load_stage = [&](int c, int s) {
        const uint32_t st = sbase + s * STAGE_BYTES;
        const long kb = (long)c * BK;
#pragma unroll
        for (int it = 0; it < 6; it++) {
            int g = it * 256 + tid;
            if (g < 1024) {
                int r = g >> 2, c16 = g & 3;
                cp16(st + r * RSTRIDE + c16 * 16,
                     Ax + (long)(tileM + r) * K + kb + c16 * 8);
            } else {
                int gb = g - 1024;
                int r = gb >> 2, c16 = gb & 3;
                cp16(st + SBOFF + r * RSTRIDE + c16 * 16,
                     Bx + (long)(tileN + r) * K + kb + c16 * 8);
            }
        }
        cp_commit();
    };

    float acc[4][8][4];
#pragma unroll
    for (int i = 0; i < 4; i++)
#pragma unroll
        for (int j = 0; j < 8; j++)
#pragma unroll
            for (int t = 0; t < 4; t++) acc[i][j][t] = 0.f;

    load_stage(0, 0);
    load_stage(1, 1);
    load_stage(2, 2);

    const int lr = lane & 15;            // ldmatrix row-within-16
    const int lc = lane >> 4;            // ldmatrix k-half

    for (int c = 0; c < NCH; c++) {
        if (c + 3 < NCH) { load_stage(c + 3, (c + 3) & 3); cp_wait<3>(); }
        else {
            const int rem = NCH - 1 - c;
            if (rem >= 2)      cp_wait<2>();
            else if (rem == 1) cp_wait<1>();
            else               cp_wait<0>();
        }
        __syncthreads();

        const uint32_t st = sbase + (c & 3) * STAGE_BYTES;
        const uint32_t sa = st, sb = st + SBOFF;

#pragma unroll
        for (int kk = 0; kk < 2; kk++) {
            const uint32_t koff = kk * 32 + lc * 16;
            // B fragments: 4 n16 groups -> 8 n8 blocks
            uint32_t bf[4][4];
#pragma unroll
            for (int g = 0; g < 4; g++) {
                uint32_t ro = (uint32_t)(wn + g * 16 + lr) * RSTRIDE + koff;
                ldm_x4(bf[g], sb + ro);
            }
#pragma unroll
            for (int mi = 0; mi < 4; mi++) {
                uint32_t ro = (uint32_t)(wm + mi * 16 + lr) * RSTRIDE + koff;
                uint32_t af[4];
                ldm_x4(af, sa + ro);
#pragma unroll
                for (int ni = 0; ni < 8; ni++) {
                    const int g = ni >> 1, o = ni & 1;
                    mma_fp16(acc[mi][ni], af, bf[g][o], bf[g][o + 2]);
                }
            }
        }
        __syncthreads();
    }

    // ---- epilogue ----
    const int er = lane >> 2;            // 0..7
    const int ec = (lane & 3) * 2;       // 0,2,4,6
#pragma unroll
    for (int mi = 0; mi < 4; mi++) {
#pragma unroll
        for (int ni = 0; ni < 8; ni++) {
            const int col = coln_base + wn + ni * 8 + ec;
            const long r0 = tileM + wm + mi * 16 + er;
            const float b0 = __ldg(bias + col), b1 = __ldg(bias + col + 1);
            float v0 = acc[mi][ni][0] + b0, v1 = acc[mi][ni][1] + b1;
            float v2 = acc[mi][ni][2] + b0, v3 = acc[mi][ni][3] + b1;
            if (FUSED && sel < 2) {
                v0 = act_elu1(v0); v1 = act_elu1(v1);
                v2 = act_elu1(v2); v3 = act_elu1(v3);
            }
            if (FUSED && sel == 0) {
                *(uint32_t*)(Ch_q + r0 * DIM_ + col)       = hpack(v0, v1);
                *(uint32_t*)(Ch_q + (r0 + 8) * DIM_ + col) = hpack(v2, v3);
            } else {
                float* o = FUSED ? ((sel == 1) ? Cf_k : Cf_v) : (Cf_out + z * sC);
                *(float2*)(o + r0 * DIM_ + col) = make_float2(v0, v1);
                *(float2*)(o + (r0 + 8) * DIM_ + col) = make_float2(v2, v3);
            }
        }
    }
}

// ---------------- P = RF @ RF^T (64x64) ------------------------------------
__global__ __launch_bounds__(256) void pmat_kernel(const float* __restrict__ RF,
                                                   float* __restrict__ P)
{
    __shared__ float RFs[64][65];
    const int tid = threadIdx.x;
    const int i  = tid / 4;
    const int j0 = (tid % 4) * 16;
    float acc[16];
#pragma unroll
    for (int j = 0; j < 16; j++) acc[j] = 0.f;

    for (int f0 = 0; f0 < FEAT; f0 += 64) {
        for (int t = tid; t < 64 * 16; t += 256) {
            int r = t / 16, c4 = (t % 16) * 4;
            float4 v = *(const float4*)(RF + (long)r * FEAT + f0 + c4);
            RFs[r][c4 + 0] = v.x;
            RFs[r][c4 + 1] = v.y;
            RFs[r][c4 + 2] = v.z;
            RFs[r][c4 + 3] = v.w;
        }
        __syncthreads();
#pragma unroll 8
        for (int f = 0; f < 64; f++) {
            float a = RFs[i][f];
#pragma unroll
            for (int j = 0; j < 16; j++)
                acc[j] = fmaf(a, RFs[j0 + j][f], acc[j]);
        }
        __syncthreads();
    }
#pragma unroll
    for (int j = 0; j < 16; j++) P[i * HD + j0 + j] = acc[j];
}

// ---------------- G partials: G(b,h) += k1[chunk]^T @ v[chunk] --------------
__global__ __launch_bounds__(256) void kv_outer_kernel(const float* __restrict__ Kmat,
                                                       const float* __restrict__ Vmat,
                                                       float* __restrict__ Gp)
{
    const int bh = blockIdx.x;
    const int b = bh / HEADS, h = bh % HEADS;
    const int split = blockIdx.y;
    const int n0 = split * (NLEN / GSPLIT);
    const int CH = 32;

    __shared__ float Ks[CH][HD];
    __shared__ float Vs[CH][HD];

    const int tid = threadIdx.x;
    const int ty = tid / 16, tx = tid % 16;
    float acc[4][4];
#pragma unroll
    for (int i = 0; i < 4; i++)
#pragma unroll
        for (int j = 0; j < 4; j++) acc[i][j] = 0.f;

    const long base = ((long)b * NLEN) * DIM_ + h * HD;

    for (int n = n0; n < n0 + NLEN / GSPLIT; n += CH) {
        for (int t = tid; t < CH * 16; t += 256) {
            int r = t / 16, c4 = (t % 16) * 4;
            *(float4*)&Ks[r][c4] = *(const float4*)(Kmat + base + (long)(n + r) * DIM_ + c4);
            *(float4*)&Vs[r][c4] = *(const float4*)(Vmat + base + (long)(n + r) * DIM_ + c4);
        }
        __syncthreads();
#pragma unroll
        for (int kk = 0; kk < CH; kk++) {
            float kr[4], vr[4];
#pragma unroll
            for (int i = 0; i < 4; i++) kr[i] = Ks[kk][ty * 4 + i];
#pragma unroll
            for (int j = 0; j < 4; j++) vr[j] = Vs[kk][tx * 4 + j];
#pragma unroll
            for (int i = 0; i < 4; i++)
#pragma unroll
                for (int j = 0; j < 4; j++)
                    acc[i][j] = fmaf(kr[i], vr[j], acc[i][j]);
        }
        __syncthreads();
    }

    float* out = Gp + ((long)split * BSZ * HEADS + bh) * HD * HD;
#pragma unroll
    for (int i = 0; i < 4; i++)
#pragma unroll
        for (int j = 0; j < 4; j++)
            out[(ty * 4 + i) * HD + tx * 4 + j] = acc[i][j];
}

// ---------------- reduce G partials, M = P @ G ------------------------------
__global__ __launch_bounds__(256) void gm_kernel(const float* __restrict__ Gp,
                                                 const float* __restrict__ P,
                                                 float* __restrict__ Mout)
{
    const int bh = blockIdx.x;
    __shared__ float Gs[HD][HD];
    __shared__ float Ps[HD][HD];
    const int tid = threadIdx.x;

    for (int t = tid; t < HD * HD; t += 256) {
        float s = 0.f;
#pragma unroll
        for (int sp = 0; sp < GSPLIT; sp++)
            s += Gp[((long)sp * BSZ * HEADS + bh) * HD * HD + t];
        Gs[t / HD][t % HD] = s;
        Ps[t / HD][t % HD] = P[t];
    }
    __syncthreads();

    const int e = tid / 4;
    const int d0 = (tid % 4) * 16;
    float acc[16];
#pragma unroll
    for (int j = 0; j < 16; j++) acc[j] = 0.f;
#pragma unroll 8
    for (int c = 0; c < HD; c++) {
        float pe = Ps[e][c];
#pragma unroll
        for (int j = 0; j < 16; j++)
            acc[j] = fmaf(pe, Gs[c][d0 + j], acc[j]);
    }
#pragma unroll
    for (int j = 0; j < 16; j++)
        Mout[(long)bh * HD * HD + e * HD + d0 + j] = acc[j];
}

// ---------------- W2t(b)[c, h*64+e] = sum_d M(b,h)[e,d] * Wo[h*64+d, c] -----
__global__ __launch_bounds__(256) void w2_kernel(const float* __restrict__ Mmat,
                                                 const float* __restrict__ Wo,
                                                 __half* __restrict__ W2t)
{
    const int bh = blockIdx.x;
    const int b = bh / HEADS, h = bh % HEADS;
    const int c0 = blockIdx.y * 128;

    __shared__ float Ms[HD][HD];
    const int tid = threadIdx.x;
    for (int t = tid; t < HD * HD; t += 256)
        Ms[t / HD][t % HD] = Mmat[(long)bh * HD * HD + t];
    __syncthreads();

    const int col = c0 + (tid & 127);
    const int e0  = (tid >> 7) * 32;
    float acc[32];
#pragma unroll
    for (int e = 0; e < 32; e++) acc[e] = 0.f;
#pragma unroll 4
    for (int d = 0; d < HD; d++) {
        float w = Wo[(long)(h * HD + d) * DIM_ + col];
#pragma unroll
        for (int e = 0; e < 32; e++)
            acc[e] = fmaf(Ms[e0 + e][d], w, acc[e]);
    }
    const long obase = (long)b * DIM_ * DIM_ + (long)col * DIM_ + h * HD + e0;
#pragma unroll
    for (int e = 0; e < 32; e++)
        W2t[obase + e] = __float2half_rn(acc[e]);
}

// ---------------- launch ----------------------------------------------------
extern "C" void kernel_launch(void* const* d_in, const int* in_sizes, int n_in,
                              void* d_out, int out_size)
{
    const float* x   = (const float*)d_in[0];
    const float* Wq  = (const float*)d_in[1];
    const float* bq  = (const float*)d_in[2];
    const float* Wk  = (const float*)d_in[3];
    const float* bk  = (const float*)d_in[4];
    const float* Wv  = (const float*)d_in[5];
    const float* bv  = (const float*)d_in[6];
    const float* Wo  = (const float*)d_in[7];
    const float* bo  = (const float*)d_in[8];
    const float* RF  = (const float*)d_in[9];
    float* out = (float*)d_out;

    __half *x16, *q116, *wt16, *w2t16;
    float *kp, *vp, *gpp, *pp, *mp;
    cudaGetSymbolAddress((void**)&x16,   g_x16);
    cudaGetSymbolAddress((void**)&q116,  g_q116);
    cudaGetSymbolAddress((void**)&kp,    g_k);
    cudaGetSymbolAddress((void**)&vp,    g_v);
    cudaGetSymbolAddress((void**)&wt16,  g_wt16);
    cudaGetSymbolAddress((void**)&w2t16, g_w2t16);
    cudaGetSymbolAddress((void**)&gpp,   g_Gpart);
    cudaGetSymbolAddress((void**)&pp,    g_P);
    cudaGetSymbolAddress((void**)&mp,    g_M);

    cudaFuncSetAttribute(gemm_tc<1>, cudaFuncAttributeMaxDynamicSharedMemorySize, GEMM_SMEM);
    cudaFuncSetAttribute(gemm_tc<0>, cudaFuncAttributeMaxDynamicSharedMemorySize, GEMM_SMEM);

    // 1) x -> fp16 (shared A for all 3 projections)
    conv_x_kernel<<<(ROWS * DIM_ / 4 + 255) / 256, 256>>>(
        (const float4*)x, (uint2*)x16, ROWS * DIM_ / 4);

    // 2) transpose weights -> fp16 (fused, z = which weight)
    conv_w_kernel<<<dim3(32, 32, 3), dim3(32, 32)>>>(Wq, Wk, Wv, wt16);

    // 3) fused QKV projection (N = 3072 concatenated)
    dim3 gq(3 * DIM_ / BN, ROWS / BM, 1);
    gemm_tc<1><<<gq, 256, GEMM_SMEM>>>(x16, wt16, bq, bk, bv,
                                       kp, vp, q116, nullptr,
                                       DIM_, 0, 0, 0);

    // 4) P = RF @ RF^T
    pmat_kernel<<<1, 256>>>(RF, pp);

    // 5) G partials: k1^T v per (b,h)
    kv_outer_kernel<<<dim3(BSZ * HEADS, GSPLIT), 256>>>(kp, vp, gpp);

    // 6) reduce + M = P @ G
    gm_kernel<<<BSZ * HEADS, 256>>>(gpp, pp, mp);

    // 7) W2t(b) = (blockdiag(M) @ Wo)^T, fp16
    w2_kernel<<<dim3(BSZ * HEADS, DIM_ / 128), 256>>>(mp, Wo, w2t16);

    // 8) final: out(b) = q1(b) @ W2(b) + bo (batched)
    dim3 gf(DIM_ / BN, NLEN / BM, BSZ);
    gemm_tc<0><<<gf, 256, GEMM_SMEM>>>(q116, w2t16, bo, nullptr, nullptr,
                                       nullptr, nullptr, nullptr, out,
                                       DIM_,
                                       (long)NLEN * DIM_, (long)DIM_ * DIM_,
                                       (long)NLEN * DIM_);
}

// round 12
// speedup vs baseline: 1.1701x; 1.1701x over previous
#include <cuda_runtime.h>
#include <cuda_fp16.h>
#include <cstdint>
#include <math.h>

// Problem constants
#define BSZ   4
#define NLEN  4096
#define DIM_  1024
#define HEADS 16
#define HD    64
#define FEAT  256
#define ROWS  (BSZ * NLEN)   // 16384
#define GSPLIT 8

// ---------------- scratch (__device__ globals; no allocation allowed) ------
__device__ __align__(16) __half g_x16[(size_t)ROWS * DIM_];
__device__ __align__(16) __half g_q116[(size_t)ROWS * DIM_];
__device__ __align__(16) float g_k[(size_t)ROWS * DIM_];
__device__ __align__(16) float g_v[(size_t)ROWS * DIM_];
__device__ __align__(16) __half g_wt16[3][(size_t)DIM_ * DIM_];   // [Wq;Wk;Wv]^T fp16
__device__ __align__(16) __half g_w2t16[(size_t)BSZ * DIM_ * DIM_];
__device__ float g_Gpart[(size_t)GSPLIT * BSZ * HEADS * HD * HD];
__device__ float g_P[HD * HD];
__device__ float g_M[(size_t)BSZ * HEADS * HD * HD];

__device__ __forceinline__ float act_elu1(float x) {
    return x > 0.f ? x + 1.f : expf(x);
}

// ======================= PTX helpers (non-'a' ISA only) =====================
__device__ __forceinline__ uint32_t smem_u32(const void* p) {
    return (uint32_t)__cvta_generic_to_shared(p);
}

__device__ __forceinline__ void cp16(uint32_t smem, const void* g) {
    asm volatile("cp.async.cg.shared.global [%0], [%1], 16;\n" :: "r"(smem), "l"(g));
}
__device__ __forceinline__ void cp_commit() {
    asm volatile("cp.async.commit_group;\n" ::: "memory");
}
template <int N>
__device__ __forceinline__ void cp_wait() {
    asm volatile("cp.async.wait_group %0;\n" :: "n"(N) : "memory");
}

__device__ __forceinline__ void ldm_x4(uint32_t* r, uint32_t addr) {
    asm volatile("ldmatrix.sync.aligned.m8n8.x4.shared.b16 {%0,%1,%2,%3}, [%4];"
                 : "=r"(r[0]), "=r"(r[1]), "=r"(r[2]), "=r"(r[3]) : "r"(addr));
}

__device__ __forceinline__ void mma_fp16(float* c, const uint32_t* a, uint32_t b0, uint32_t b1) {
    asm volatile(
        "mma.sync.aligned.m16n8k16.row.col.f32.f16.f16.f32 "
        "{%0,%1,%2,%3}, {%4,%5,%6,%7}, {%8,%9}, {%0,%1,%2,%3};"
        : "+f"(c[0]), "+f"(c[1]), "+f"(c[2]), "+f"(c[3])
        : "r"(a[0]), "r"(a[1]), "r"(a[2]), "r"(a[3]), "r"(b0), "r"(b1));
}

__device__ __forceinline__ uint32_t hpack(float a, float b) {
    __half h0 = __float2half_rn(a), h1 = __float2half_rn(b);
    return (uint32_t)__half_as_ushort(h0) | ((uint32_t)__half_as_ushort(h1) << 16);
}

// ======================= conversion kernels ================================
__global__ __launch_bounds__(256) void conv_x_kernel(const float4* __restrict__ x,
                                                     uint2* __restrict__ xo, int n4)
{
    int i = blockIdx.x * 256 + threadIdx.x;
    if (i >= n4) return;
    float4 v = x[i];
    uint2 H;
    H.x = hpack(v.x, v.y);
    H.y = hpack(v.z, v.w);
    xo[i] = H;
}

// transpose + fp16: Wt[n,k] = W[k,n]; blockIdx.z selects Wq/Wk/Wv
__global__ __launch_bounds__(1024) void conv_w_kernel(const float* __restrict__ W0,
                                                      const float* __restrict__ W1,
                                                      const float* __restrict__ W2,
                                                      __half* __restrict__ Wt)
{
    __shared__ float t[32][33];
    const float* W = (blockIdx.z == 0) ? W0 : (blockIdx.z == 1) ? W1 : W2;
    int tx = threadIdx.x, ty = threadIdx.y;
    int k = blockIdx.y * 32 + ty, n = blockIdx.x * 32 + tx;
    t[ty][tx] = W[(long)k * DIM_ + n];
    __syncthreads();
    float v = t[tx][ty];
    long o = (long)blockIdx.z * DIM_ * DIM_
           + (long)(blockIdx.x * 32 + ty) * DIM_ + blockIdx.y * 32 + tx;
    Wt[o] = __float2half_rn(v);
}

// ======================= mma.sync fp16 GEMM (R8 geometry) ===================
// Block tile 128x128, BK=32, 8 warps (warp tile 64x32), 4-stage cp.async.
// Stage = 20KB; 4 stages = 80KB -> 2 CTAs/SM (16 warps).
#define BK 32
#define RSTRIDE 80                       // 64B row + 16B pad (conflict-free ldmatrix)
#define SA 0
#define SB (128 * RSTRIDE)
#define STAGE_BYTES (2 * 128 * RSTRIDE)  // 20480
#define NSTAGES 4
#define GEMM_SMEM (NSTAGES * STAGE_BYTES)

// FUSED==1: QKV — B = [Wq;Wk;Wv]^T (3072 x 1024); tile's N-range selects:
//   q -> fp16 (+act), k -> fp32 (+act), v -> fp32.
// FUSED==0: final batched GEMM, fp32 out, no act; z = batch.
template <int FUSED>
__global__ __launch_bounds__(256, 2) void gemm_tc(
    const __half* __restrict__ Ax, const __half* __restrict__ Bx,
    const float* __restrict__ bias0, const float* __restrict__ bias1,
    const float* __restrict__ bias2,
    float* __restrict__ Cf_k, float* __restrict__ Cf_v,
    __half* __restrict__ Ch_q, float* __restrict__ Cf_out,
    int K, long sA, long sB, long sC)
{
    extern __shared__ char dynsmem[];
    const uint32_t sbase = smem_u32(dynsmem);

    const int tid = threadIdx.x;
    const int wid = tid >> 5, lane = tid & 31;
    const long z = blockIdx.z;
    if (!FUSED) { Ax += z * sA; Bx += z * sB; }

    const int tileM = blockIdx.y * 128;
    const int tileN = blockIdx.x * 128;
    const int wm = (wid >> 2) * 64;      // warp M offset in tile
    const int wn = (wid & 3) * 32;       // warp N offset in tile

    // output selection (uniform per CTA)
    int sel;                             // 0:q 1:k 2:v 3:final
    int coln_base;
    const float* bias;
    if (FUSED) {
        sel = tileN >> 10;
        coln_base = tileN & 1023;
        bias = (sel == 0) ? bias0 : (sel == 1) ? bias1 : bias2;
    } else {
        sel = 3;
        coln_base = tileN;
        bias = bias0;
    }

    const int NCH = K / BK;

    // ---- loader: 1024 x 16B granules per stage (A + B, 128 rows x 4 segs) ----
    auto load_stage = [&](int c, int s) {
        const uint32_t st = sbase + s * STAGE_BYTES;
        const long kb = (long)c * BK;
#pragma unroll
        for (int it = 0; it < 4; it++) {
            int g = it * 256 + tid;
            int which = g >> 9;          // 0:A 1:B
            int r = (g >> 2) & 127;
            int c16 = g & 3;
            uint32_t dst = st + which * (128 * RSTRIDE) + r * RSTRIDE + c16 * 16;
            const __half* src = which ? (Bx + (long)(tileN + r) * K + kb + c16 * 8)
                                      : (Ax + (long)(tileM + r) * K + kb + c16 * 8);
            cp16(dst, src);
        }
        cp_commit();
    };

    float acc[4][4][4];
#pragma unroll
    for (int i = 0; i < 4; i++)
#pragma unroll
        for (int j = 0; j < 4; j++)
#pragma unroll
            for (int t = 0; t < 4; t++) acc[i][j][t] = 0.f;

    load_stage(0, 0);
    load_stage(1, 1);
    load_stage(2, 2);

    const int lr = lane & 15;            // ldmatrix row-within-16
    const int lc = lane >> 4;            // ldmatrix k-half

    for (int c = 0; c < NCH; c++) {
        if (c + 3 < NCH) { load_stage(c + 3, (c + 3) & 3); cp_wait<3>(); }
        else {
            const int rem = NCH - 1 - c;
            if (rem >= 2)      cp_wait<2>();
            else if (rem == 1) cp_wait<1>();
            else               cp_wait<0>();
        }
        __syncthreads();

        const uint32_t st = sbase + (c & 3) * STAGE_BYTES;
        const uint32_t sa = st + SA, sb = st + SB;

#pragma unroll
        for (int kk = 0; kk < 2; kk++) {
            const uint32_t koff = kk * 32 + lc * 16;
            uint32_t bf[2][4];
#pragma unroll
            for (int g = 0; g < 2; g++) {
                uint32_t ro = (uint32_t)(wn + g * 16 + lr) * RSTRIDE + koff;
                ldm_x4(bf[g], sb + ro);
            }
#pragma unroll
            for (int mi = 0; mi < 4; mi++) {
                uint32_t ro = (uint32_t)(wm + mi * 16 + lr) * RSTRIDE + koff;
                uint32_t af[4];
                ldm_x4(af, sa + ro);
#pragma unroll
                for (int ni = 0; ni < 4; ni++) {
                    const int g = ni >> 1, o = ni & 1;
                    mma_fp16(acc[mi][ni], af, bf[g][o], bf[g][o + 2]);
                }
            }
        }
        __syncthreads();
    }

    // ---- epilogue ----
    const int er = lane >> 2;            // 0..7
    const int ec = (lane & 3) * 2;       // 0,2,4,6
#pragma unroll
    for (int mi = 0; mi < 4; mi++) {
#pragma unroll
        for (int ni = 0; ni < 4; ni++) {
            const int col = coln_base + wn + ni * 8 + ec;
            const long r0 = tileM + wm + mi * 16 + er;
            const float b0 = __ldg(bias + col), b1 = __ldg(bias + col + 1);
            float v0 = acc[mi][ni][0] + b0, v1 = acc[mi][ni][1] + b1;
            float v2 = acc[mi][ni][2] + b0, v3 = acc[mi][ni][3] + b1;
            if (FUSED && sel < 2) {
                v0 = act_elu1(v0); v1 = act_elu1(v1);
                v2 = act_elu1(v2); v3 = act_elu1(v3);
            }
            if (FUSED && sel == 0) {
                *(uint32_t*)(Ch_q + r0 * DIM_ + col)       = hpack(v0, v1);
                *(uint32_t*)(Ch_q + (r0 + 8) * DIM_ + col) = hpack(v2, v3);
            } else {
                float* o = FUSED ? ((sel == 1) ? Cf_k : Cf_v) : (Cf_out + z * sC);
                *(float2*)(o + r0 * DIM_ + col) = make_float2(v0, v1);
                *(float2*)(o + (r0 + 8) * DIM_ + col) = make_float2(v2, v3);
            }
        }
    }
}

// ---------------- P = RF @ RF^T (64x64), parallel 4x4 grid -----------------
// Block (bi,bj) computes P[bi*16..+16][bj*16..+16]; K=256 staged in smem.
#define PM_PAD 258
__global__ __launch_bounds__(256) void pmat_kernel(const float* __restrict__ RF,
                                                   float* __restrict__ P)
{
    __shared__ float Ri[16][PM_PAD];
    __shared__ float Rj[16][PM_PAD];
    const int tid = threadIdx.x;
    const int bi = blockIdx.x * 16, bj = blockIdx.y * 16;

    // load 16 rows x 256 cols each (coalesced float4)
    for (int t = tid; t < 16 * 64; t += 256) {
        int r = t >> 6, c4 = (t & 63) * 4;
        float4 vi = *(const float4*)(RF + (long)(bi + r) * FEAT + c4);
        float4 vj = *(const float4*)(RF + (long)(bj + r) * FEAT + c4);
        Ri[r][c4] = vi.x; Ri[r][c4 + 1] = vi.y; Ri[r][c4 + 2] = vi.z; Ri[r][c4 + 3] = vi.w;
        Rj[r][c4] = vj.x; Rj[r][c4 + 1] = vj.y; Rj[r][c4 + 2] = vj.z; Rj[r][c4 + 3] = vj.w;
    }
    __syncthreads();

    const int i = tid >> 4, j = tid & 15;
    float acc = 0.f;
#pragma unroll 16
    for (int f = 0; f < FEAT; f++)
        acc = fmaf(Ri[i][f], Rj[j][f], acc);
    P[(bi + i) * HD + bj + j] = acc;
}

// ---------------- G partials: G(b,h) += k1[chunk]^T @ v[chunk] --------------
__global__ __launch_bounds__(256) void kv_outer_kernel(const float* __restrict__ Kmat,
                                                       const float* __restrict__ Vmat,
                                                       float* __restrict__ Gp)
{
    const int bh = blockIdx.x;
    const int b = bh / HEADS, h = bh % HEADS;
    const int split = blockIdx.y;
    const int n0 = split * (NLEN / GSPLIT);
    const int CH = 32;

    __shared__ float Ks[CH][HD];
    __shared__ float Vs[CH][HD];

    const int tid = threadIdx.x;
    const int ty = tid / 16, tx = tid % 16;
    float acc[4][4];
#pragma unroll
    for (int i = 0; i < 4; i++)
#pragma unroll
        for (int j = 0; j < 4; j++) acc[i][j] = 0.f;

    const long base = ((long)b * NLEN) * DIM_ + h * HD;

    for (int n = n0; n < n0 + NLEN / GSPLIT; n += CH) {
        for (int t = tid; t < CH * 16; t += 256) {
            int r = t / 16, c4 = (t % 16) * 4;
            *(float4*)&Ks[r][c4] = *(const float4*)(Kmat + base + (long)(n + r) * DIM_ + c4);
            *(float4*)&Vs[r][c4] = *(const float4*)(Vmat + base + (long)(n + r) * DIM_ + c4);
        }
        __syncthreads();
#pragma unroll
        for (int kk = 0; kk < CH; kk++) {
            float kr[4], vr[4];
#pragma unroll
            for (int i = 0; i < 4; i++) kr[i] = Ks[kk][ty * 4 + i];
#pragma unroll
            for (int j = 0; j < 4; j++) vr[j] = Vs[kk][tx * 4 + j];
#pragma unroll
            for (int i = 0; i < 4; i++)
#pragma unroll
                for (int j = 0; j < 4; j++)
                    acc[i][j] = fmaf(kr[i], vr[j], acc[i][j]);
        }
        __syncthreads();
    }

    float* out = Gp + ((long)split * BSZ * HEADS + bh) * HD * HD;
#pragma unroll
    for (int i = 0; i < 4; i++)
#pragma unroll
        for (int j = 0; j < 4; j++)
            out[(ty * 4 + i) * HD + tx * 4 + j] = acc[i][j];
}

// ---------------- reduce G partials, M = P @ G ------------------------------
__global__ __launch_bounds__(256) void gm_kernel(const float* __restrict__ Gp,
                                                 const float* __restrict__ P,
                                                 float* __restrict__ Mout)
{
    const int bh = blockIdx.x;
    __shared__ float Gs[HD][HD];
    __shared__ float Ps[HD][HD];
    const int tid = threadIdx.x;

    for (int t = tid; t < HD * HD; t += 256) {
        float s = 0.f;
#pragma unroll
        for (int sp = 0; sp < GSPLIT; sp++)
            s += Gp[((long)sp * BSZ * HEADS + bh) * HD * HD + t];
        Gs[t / HD][t % HD] = s;
        Ps[t / HD][t % HD] = P[t];
    }
    __syncthreads();

    const int e = tid / 4;
    const int d0 = (tid % 4) * 16;
    float acc[16];
#pragma unroll
    for (int j = 0; j < 16; j++) acc[j] = 0.f;
#pragma unroll 8
    for (int c = 0; c < HD; c++) {
        float pe = Ps[e][c];
#pragma unroll
        for (int j = 0; j < 16; j++)
            acc[j] = fmaf(pe, Gs[c][d0 + j], acc[j]);
    }
#pragma unroll
    for (int j = 0; j < 16; j++)
        Mout[(long)bh * HD * HD + e * HD + d0 + j] = acc[j];
}

// ---------------- W2t(b)[c, h*64+e] = sum_d M(b,h)[e,d] * Wo[h*64+d, c] -----
__global__ __launch_bounds__(256) void w2_kernel(const float* __restrict__ Mmat,
                                                 const float* __restrict__ Wo,
                                                 __half* __restrict__ W2t)
{
    const int bh = blockIdx.x;
    const int b = bh / HEADS, h = bh % HEADS;
    const int c0 = blockIdx.y * 128;

    __shared__ float Ms[HD][HD];
    const int tid = threadIdx.x;
    for (int t = tid; t < HD * HD; t += 256)
        Ms[t / HD][t % HD] = Mmat[(long)bh * HD * HD + t];
    __syncthreads();

    const int col = c0 + (tid & 127);
    const int e0  = (tid >> 7) * 32;
    float acc[32];
#pragma unroll
    for (int e = 0; e < 32; e++) acc[e] = 0.f;
#pragma unroll 4
    for (int d = 0; d < HD; d++) {
        float w = Wo[(long)(h * HD + d) * DIM_ + col];
#pragma unroll
        for (int e = 0; e < 32; e++)
            acc[e] = fmaf(Ms[e0 + e][d], w, acc[e]);
    }
    const long obase = (long)b * DIM_ * DIM_ + (long)col * DIM_ + h * HD + e0;
#pragma unroll
    for (int e = 0; e < 32; e++)
        W2t[obase + e] = __float2half_rn(acc[e]);
}

// ---------------- launch ----------------------------------------------------
extern "C" void kernel_launch(void* const* d_in, const int* in_sizes, int n_in,
                              void* d_out, int out_size)
{
    const float* x   = (const float*)d_in[0];
    const float* Wq  = (const float*)d_in[1];
    const float* bq  = (const float*)d_in[2];
    const float* Wk  = (const float*)d_in[3];
    const float* bk  = (const float*)d_in[4];
    const float* Wv  = (const float*)d_in[5];
    const float* bv  = (const float*)d_in[6];
    const float* Wo  = (const float*)d_in[7];
    const float* bo  = (const float*)d_in[8];
    const float* RF  = (const float*)d_in[9];
    float* out = (float*)d_out;

    __half *x16, *q116, *wt16, *w2t16;
    float *kp, *vp, *gpp, *pp, *mp;
    cudaGetSymbolAddress((void**)&x16,   g_x16);
    cudaGetSymbolAddress((void**)&q116,  g_q116);
    cudaGetSymbolAddress((void**)&kp,    g_k);
    cudaGetSymbolAddress((void**)&vp,    g_v);
    cudaGetSymbolAddress((void**)&wt16,  g_wt16);
    cudaGetSymbolAddress((void**)&w2t16, g_w2t16);
    cudaGetSymbolAddress((void**)&gpp,   g_Gpart);
    cudaGetSymbolAddress((void**)&pp,    g_P);
    cudaGetSymbolAddress((void**)&mp,    g_M);

    cudaFuncSetAttribute(gemm_tc<1>, cudaFuncAttributeMaxDynamicSharedMemorySize, GEMM_SMEM);
    cudaFuncSetAttribute(gemm_tc<0>, cudaFuncAttributeMaxDynamicSharedMemorySize, GEMM_SMEM);

    // 1) x -> fp16 (shared A for all 3 projections)
    conv_x_kernel<<<(ROWS * DIM_ / 4 + 255) / 256, 256>>>(
        (const float4*)x, (uint2*)x16, ROWS * DIM_ / 4);

    // 2) transpose weights -> fp16 (fused, z = which weight)
    conv_w_kernel<<<dim3(32, 32, 3), dim3(32, 32)>>>(Wq, Wk, Wv, wt16);

    // 3) fused QKV projection (N = 3072 concatenated), 128x128 tiles, 2 CTA/SM
    dim3 gq(3 * DIM_ / 128, ROWS / 128, 1);
    gemm_tc<1><<<gq, 256, GEMM_SMEM>>>(x16, wt16, bq, bk, bv,
                                       kp, vp, q116, nullptr,
                                       DIM_, 0, 0, 0);

    // 4) P = RF @ RF^T (parallel)
    pmat_kernel<<<dim3(4, 4), 256>>>(RF, pp);

    // 5) G partials: k1^T v per (b,h)
    kv_outer_kernel<<<dim3(BSZ * HEADS, GSPLIT), 256>>>(kp, vp, gpp);

    // 6) reduce + M = P @ G
    gm_kernel<<<BSZ * HEADS, 256>>>(gpp, pp, mp);

    // 7) W2t(b) = (blockdiag(M) @ Wo)^T, fp16
    w2_kernel<<<dim3(BSZ * HEADS, DIM_ / 128), 256>>>(mp, Wo, w2t16);

    // 8) final: out(b) = q1(b) @ W2(b) + bo (batched)
    dim3 gf(DIM_ / 128, NLEN / 128, BSZ);
    gemm_tc<0><<<gf, 256, GEMM_SMEM>>>(q116, w2t16, bo, nullptr, nullptr,
                                       nullptr, nullptr, nullptr, out,
                                       DIM_,
                                       (long)NLEN * DIM_, (long)DIM_ * DIM_,
                                       (long)NLEN * DIM_);
}